// round 3
// baseline (speedup 1.0000x reference)
#include <cuda_runtime.h>
#include <cuda_bf16.h>
#include <math.h>
#include <stdint.h>

// Problem constants (fixed shapes)
constexpr int Bb  = 2;
constexpr int Lc  = 4096;
constexpr int Dc  = 2048;
constexpr int Hh  = 32;
constexpr int Kc  = 16;
constexpr int HDc = 64;
constexpr int NMBc = 256;           // L / K
constexpr int Mrows = Bb * Lc;      // 8192

// Scratch (device globals; allocation in kernel_launch is forbidden)
__device__ float g_q  [(size_t)Bb*Hh*NMBc*Kc*HDc];   // scan layout [b][h][n][k][d]
__device__ float g_k  [(size_t)Bb*Hh*NMBc*Kc*HDc];
__device__ float g_v  [(size_t)Bb*Hh*NMBc*Kc*HDc];
__device__ float g_eta[(size_t)Bb*Hh*NMBc*Kc];
__device__ float g_y  [(size_t)Bb*Lc*Dc];            // scan output, token layout

// bf16 hi/lo split operands for tensor-core GEMMs
__device__ __nv_bfloat16 g_ah [(size_t)Mrows*Dc];
__device__ __nv_bfloat16 g_al [(size_t)Mrows*Dc];
__device__ __nv_bfloat16 g_wqh[(size_t)Dc*Dc];
__device__ __nv_bfloat16 g_wql[(size_t)Dc*Dc];
__device__ __nv_bfloat16 g_wkh[(size_t)Dc*Dc];
__device__ __nv_bfloat16 g_wkl[(size_t)Dc*Dc];
__device__ __nv_bfloat16 g_wvh[(size_t)Dc*Dc];
__device__ __nv_bfloat16 g_wvl[(size_t)Dc*Dc];
__device__ __nv_bfloat16 g_woh[(size_t)Dc*Dc];
__device__ __nv_bfloat16 g_wol[(size_t)Dc*Dc];
__device__ __nv_bfloat16 g_xnh[(size_t)Mrows*Dc];
__device__ __nv_bfloat16 g_xnl[(size_t)Mrows*Dc];

// ---------------------------------------------------------------------------
// fp32 -> bf16 (hi, lo) split conversion.  n must be a multiple of 1024.
// ---------------------------------------------------------------------------
__global__ __launch_bounds__(256) void conv_kernel(
    const float* __restrict__ x, __nv_bfloat16* __restrict__ hi,
    __nv_bfloat16* __restrict__ lo, int n)
{
    int i = (blockIdx.x*256 + threadIdx.x)*4;
    if (i >= n) return;
    float4 v = *(const float4*)&x[i];
    __nv_bfloat16 h[4], l[4];
    float vv[4] = {v.x, v.y, v.z, v.w};
#pragma unroll
    for (int j = 0; j < 4; j++) {
        h[j] = __float2bfloat16_rn(vv[j]);
        l[j] = __float2bfloat16_rn(vv[j] - __bfloat162float(h[j]));
    }
    *(uint2*)&hi[i] = *(uint2*)h;
    *(uint2*)&lo[i] = *(uint2*)l;
}

// ---------------------------------------------------------------------------
// Tensor-core GEMM: C(8192x2048) = (Ah+Al)(8192x2048) @ (Bh+Bl)(2048x2048) + bias
// 3-pass bf16 split: Ah@Bh + Ah@Bl + Al@Bh  (error ~2^-18 per element)
// mode 0: row-major C; mode 1: permute into scan layout [b][h][n][k][d]
// CTA tile 128x128, BK=16, 2-stage cp.async pipeline, 8 warps of 64x32.
// ---------------------------------------------------------------------------
#define LDSM4(R, addr) asm volatile( \
    "ldmatrix.sync.aligned.m8n8.x4.shared.b16 {%0,%1,%2,%3}, [%4];\n" \
    : "=r"((R)[0]), "=r"((R)[1]), "=r"((R)[2]), "=r"((R)[3]) : "r"(addr))
#define LDSM4T(R, addr) asm volatile( \
    "ldmatrix.sync.aligned.m8n8.x4.trans.shared.b16 {%0,%1,%2,%3}, [%4];\n" \
    : "=r"((R)[0]), "=r"((R)[1]), "=r"((R)[2]), "=r"((R)[3]) : "r"(addr))
#define MMA16816(d, a, b0, b1) asm volatile( \
    "mma.sync.aligned.m16n8k16.row.col.f32.bf16.bf16.f32 " \
    "{%0,%1,%2,%3},{%4,%5,%6,%7},{%8,%9},{%0,%1,%2,%3};\n" \
    : "+f"((d)[0]), "+f"((d)[1]), "+f"((d)[2]), "+f"((d)[3]) \
    : "r"((a)[0]), "r"((a)[1]), "r"((a)[2]), "r"((a)[3]), "r"(b0), "r"(b1))

__device__ __forceinline__ void cp16(uint32_t dst, const void* src) {
    asm volatile("cp.async.cg.shared.global [%0], [%1], 16;\n" :: "r"(dst), "l"(src));
}

__global__ __launch_bounds__(256) void hgemm_kernel(
    const __nv_bfloat16* __restrict__ Ah, const __nv_bfloat16* __restrict__ Al,
    const __nv_bfloat16* __restrict__ Bh, const __nv_bfloat16* __restrict__ Bl,
    const float* __restrict__ bias, float* __restrict__ C, int mode)
{
    // layout: smem[mat][stage][2048] bf16, mat: 0=Ah 1=Al 2=Bh 3=Bl
    __shared__ __align__(16) __nv_bfloat16 smem[4*2*2048];
    const int tid = threadIdx.x, lane = tid & 31, wid = tid >> 5;
    const int wm = wid >> 2, wn = wid & 3;
    const int row0 = blockIdx.y*128, col0 = blockIdx.x*128;
    const uint32_t sbase = (uint32_t)__cvta_generic_to_shared(smem);
    // byte strides: matrix stride 8192B, stage stride 4096B

    // ---- prefetch (global->smem) thread mapping ----
    const int pr = tid >> 1, pc = tid & 1;        // A: row 0..127, chunk 0..1
    const int pk = tid >> 4, pcb = tid & 15;      // B: k 0..15, chunk 0..15
    const __nv_bfloat16* gAh = Ah + (size_t)(row0+pr)*Dc + pc*8;
    const __nv_bfloat16* gAl = Al + (size_t)(row0+pr)*Dc + pc*8;
    const __nv_bfloat16* gBh = Bh + (size_t)pk*Dc + col0 + pcb*8;
    const __nv_bfloat16* gBl = Bl + (size_t)pk*Dc + col0 + pcb*8;
    const uint32_t dA = sbase + (uint32_t)(pr*16 + 8*(pc ^ ((pr>>2)&1)))*2;
    const uint32_t dB = sbase + 2*8192 + (uint32_t)(pk*128 + 8*(pcb ^ (pk&7)))*2;

    // ---- ldmatrix per-lane addresses (stage 0; add 4096 for stage 1) ----
    const int ar = lane & 15, ac = lane >> 4;
    uint32_t adA[4];
#pragma unroll
    for (int mi = 0; mi < 4; mi++) {
        int r = wm*64 + mi*16 + ar;
        adA[mi] = sbase + (uint32_t)(r*16 + 8*(ac ^ ((r>>2)&1)))*2;
    }
    const int bk = (lane & 7) + ((lane >> 3) & 1)*8;
    uint32_t adB[2];
#pragma unroll
    for (int nj = 0; nj < 2; nj++) {
        int c = wn*4 + nj*2 + ((lane >> 4) & 1);
        adB[nj] = sbase + 2*8192 + (uint32_t)(bk*128 + 8*(c ^ (bk & 7)))*2;
    }

    float acc[4][4][4];
#pragma unroll
    for (int i = 0; i < 4; i++)
#pragma unroll
        for (int j = 0; j < 4; j++)
#pragma unroll
            for (int k = 0; k < 4; k++) acc[i][j][k] = 0.f;

    constexpr int KT = Dc / 16;   // 128

    // prefetch stage 0
    {
        cp16(dA,         gAh);
        cp16(dA + 8192,  gAl);
        cp16(dB,         gBh);
        cp16(dB + 8192,  gBl);
        asm volatile("cp.async.commit_group;\n");
    }

    for (int kt = 0; kt < KT; kt++) {
        if (kt + 1 < KT) {
            const uint32_t so = ((kt+1) & 1)*4096;
            const size_t goA = (size_t)(kt+1)*16;
            const size_t goB = (size_t)(kt+1)*16*Dc;
            cp16(dA + so,        gAh + goA);
            cp16(dA + so + 8192, gAl + goA);
            cp16(dB + so,        gBh + goB);
            cp16(dB + so + 8192, gBl + goB);
            asm volatile("cp.async.commit_group;\n");
            asm volatile("cp.async.wait_group 1;\n");
        } else {
            asm volatile("cp.async.wait_group 0;\n");
        }
        __syncthreads();

        const uint32_t so = (kt & 1)*4096;
        uint32_t ah[4][4], al[4][4], bh[2][4], bl[2][4];
#pragma unroll
        for (int mi = 0; mi < 4; mi++) {
            LDSM4(ah[mi], adA[mi] + so);
            LDSM4(al[mi], adA[mi] + so + 8192);
        }
#pragma unroll
        for (int nj = 0; nj < 2; nj++) {
            LDSM4T(bh[nj], adB[nj] + so);
            LDSM4T(bl[nj], adB[nj] + so + 8192);
        }
#pragma unroll
        for (int mi = 0; mi < 4; mi++) {
#pragma unroll
            for (int ni = 0; ni < 4; ni++) {
                const int q = ni >> 1, hb = (ni & 1)*2;
                MMA16816(acc[mi][ni], ah[mi], bh[q][hb], bh[q][hb+1]);
                MMA16816(acc[mi][ni], ah[mi], bl[q][hb], bl[q][hb+1]);
                MMA16816(acc[mi][ni], al[mi], bh[q][hb], bh[q][hb+1]);
            }
        }
        __syncthreads();
    }

    // ---- epilogue ----
    const int g = lane >> 2, t2 = (lane & 3)*2;
#pragma unroll
    for (int mi = 0; mi < 4; mi++) {
        const int r1 = row0 + wm*64 + mi*16 + g;
        const int r2 = r1 + 8;
#pragma unroll
        for (int ni = 0; ni < 4; ni++) {
            const int col = col0 + wn*32 + ni*8 + t2;
            const float2 bv = *(const float2*)&bias[col];
            float2 v0 = make_float2(acc[mi][ni][0] + bv.x, acc[mi][ni][1] + bv.y);
            float2 v1 = make_float2(acc[mi][ni][2] + bv.x, acc[mi][ni][3] + bv.y);
            if (mode == 0) {
                *(float2*)&C[(size_t)r1*Dc + col] = v0;
                *(float2*)&C[(size_t)r2*Dc + col] = v1;
            } else {
                const int h = col >> 6, d = col & 63;
                {
                    int b = r1 >> 12, l = r1 & 4095, n = l >> 4, kk = l & 15;
                    size_t o = ((((size_t)(b*Hh + h))*NMBc + n)*Kc + kk)*HDc + d;
                    *(float2*)&C[o] = v0;
                }
                {
                    int b = r2 >> 12, l = r2 & 4095, n = l >> 4, kk = l & 15;
                    size_t o = ((((size_t)(b*Hh + h))*NMBc + n)*Kc + kk)*HDc + d;
                    *(float2*)&C[o] = v1;
                }
            }
        }
    }
}

// ---------------------------------------------------------------------------
// eta = sigmoid(hs . lr_w[h] + lr_b[h]) / (HD*K)
// ---------------------------------------------------------------------------
__global__ __launch_bounds__(256) void lr_kernel(
    const float* __restrict__ hs, const float* __restrict__ lr_w,
    const float* __restrict__ lr_b)
{
    __shared__ __align__(16) float rowbuf[Dc];
    const int t = blockIdx.x;
    const int tid = threadIdx.x;
    const float* xr = hs + (size_t)t*Dc;
    for (int i = tid*4; i < Dc; i += 1024)
        *(float4*)&rowbuf[i] = *(const float4*)&xr[i];
    __syncthreads();

    const int wid = tid >> 5, lane = tid & 31;
    const int b = t >> 12, l = t & 4095, n = l >> 4, kk = l & 15;
    for (int h = wid; h < Hh; h += 8) {
        const float* w = lr_w + (size_t)h*Dc;
        float s = 0.f;
        for (int i = lane; i < Dc; i += 32) s += rowbuf[i]*w[i];
#pragma unroll
        for (int o = 16; o > 0; o >>= 1) s += __shfl_xor_sync(0xffffffffu, s, o);
        if (lane == 0) {
            float x = s + lr_b[h];
            float sig = 1.f/(1.f+expf(-x));
            g_eta[(((size_t)(b*Hh + h))*NMBc + n)*Kc + kk] = sig * (1.f/1024.f);
        }
    }
}

// ---------------------------------------------------------------------------
// Per (token, head): L2-normalize Q,K; XV <- w*((v-k)-mu)/(std+1e-8)+b+k
// ---------------------------------------------------------------------------
__global__ __launch_bounds__(256) void norm_kernel(
    const float* __restrict__ tnw, const float* __restrict__ tnb)
{
    const int wg   = blockIdx.x*8 + (threadIdx.x >> 5);
    const int lane = threadIdx.x & 31;
    const size_t base = (size_t)wg * 64;
    const int h = (wg >> 12) & 31;

    float q0 = g_q[base+lane], q1 = g_q[base+lane+32];
    float k0 = g_k[base+lane], k1 = g_k[base+lane+32];
    float v0 = g_v[base+lane], v1 = g_v[base+lane+32];

    float s = q0*q0 + q1*q1;
#pragma unroll
    for (int o = 16; o > 0; o >>= 1) s += __shfl_xor_sync(0xffffffffu, s, o);
    float inv = 1.f / fmaxf(sqrtf(s), 1e-12f);
    q0 *= inv; q1 *= inv;

    s = k0*k0 + k1*k1;
#pragma unroll
    for (int o = 16; o > 0; o >>= 1) s += __shfl_xor_sync(0xffffffffu, s, o);
    inv = 1.f / fmaxf(sqrtf(s), 1e-12f);
    k0 *= inv; k1 *= inv;

    float d0 = v0 - k0, d1 = v1 - k1;
    s = d0 + d1;
#pragma unroll
    for (int o = 16; o > 0; o >>= 1) s += __shfl_xor_sync(0xffffffffu, s, o);
    float mu = s * (1.f/64.f);
    float e0 = d0 - mu, e1 = d1 - mu;
    s = e0*e0 + e1*e1;
#pragma unroll
    for (int o = 16; o > 0; o >>= 1) s += __shfl_xor_sync(0xffffffffu, s, o);
    float stdv = sqrtf(s * (1.f/63.f));       // ddof=1
    float den = stdv + 1e-8f;

    float w0 = tnw[h*64+lane], w1 = tnw[h*64+lane+32];
    float b0 = tnb[h*64+lane], b1v = tnb[h*64+lane+32];
    float nv0 = w0*(e0/den) + b0  + k0;
    float nv1 = w1*(e1/den) + b1v + k1;

    g_q[base+lane] = q0; g_q[base+lane+32] = q1;
    g_k[base+lane] = k0; g_k[base+lane+32] = k1;
    g_v[base+lane] = nv0; g_v[base+lane+32] = nv1;
}

// ---------------------------------------------------------------------------
// Sequential TTT scan. One CTA per (b,h). 256 threads.
// ---------------------------------------------------------------------------
__global__ __launch_bounds__(256) void scan_kernel(
    const float* __restrict__ W1g, const float* __restrict__ b1g,
    const float* __restrict__ tnw, const float* __restrict__ tnb)
{
    __shared__ __align__(16) float W1s[64*64];
    __shared__ __align__(16) float xqs[1024];
    __shared__ __align__(16) float xks[1024];
    __shared__ __align__(16) float grads[1024];
    __shared__ __align__(16) float zs[1024];
    __shared__ __align__(16) float xhs[1024];
    __shared__ __align__(16) float xkTs[64*17];
    __shared__ __align__(16) float Ms[256];
    __shared__ float b1s[64], lnw[64], lnb[64], etas[16];
    __shared__ float mus[16], stds[16], sg1[16], sg2[16], mu2[16], std2[16];

    const int bh = blockIdx.x;
    const int b = bh >> 5, h = bh & 31;
    const int tid = threadIdx.x;
    const int c = tid & 63, q4 = tid >> 6;
    const int r0 = q4 * 4;

    for (int i = tid; i < 4096; i += 256) W1s[i] = W1g[(size_t)h*4096 + i];
    if (tid < 64) {
        b1s[tid] = b1g[h*64 + tid];
        lnw[tid] = tnw[h*64 + tid];
        lnb[tid] = tnb[h*64 + tid];
    }
    __syncthreads();

    const size_t tile0 = (size_t)bh * (NMBc * 1024);

    for (int n = 0; n < NMBc; n++) {
        const size_t tb = tile0 + (size_t)n * 1024;
        for (int idx = tid; idx < 1024; idx += 256) {
            float vq = g_q[tb+idx];
            float vk = g_k[tb+idx];
            float vv = g_v[tb+idx];
            xqs[idx] = vq; xks[idx] = vk; grads[idx] = vv;
            xkTs[(idx & 63)*17 + (idx >> 6)] = vk;
        }
        if (tid < 16) etas[tid] = g_eta[((size_t)bh*NMBc + n)*Kc + tid];
        __syncthreads();

        {
            float a0=0.f,a1=0.f,a2=0.f,a3=0.f;
#pragma unroll 8
            for (int k = 0; k < 64; k++) {
                float w = W1s[k*64 + c];
                a0 += xks[(r0+0)*64+k]*w;
                a1 += xks[(r0+1)*64+k]*w;
                a2 += xks[(r0+2)*64+k]*w;
                a3 += xks[(r0+3)*64+k]*w;
            }
            float bb = b1s[c];
            zs[(r0+0)*64+c] = a0+bb;
            zs[(r0+1)*64+c] = a1+bb;
            zs[(r0+2)*64+c] = a2+bb;
            zs[(r0+3)*64+c] = a3+bb;
        }
        __syncthreads();

        {
            int r = tid >> 4, i2 = tid & 15;
            float4 v = *(const float4*)&zs[r*64 + i2*4];
            float s = v.x+v.y+v.z+v.w;
#pragma unroll
            for (int o = 8; o > 0; o >>= 1) s += __shfl_xor_sync(0xffffffffu, s, o);
            float mu = s * (1.f/64.f);
            float dx=v.x-mu, dy=v.y-mu, dz=v.z-mu, dw=v.w-mu;
            float ss = dx*dx+dy*dy+dz*dz+dw*dw;
#pragma unroll
            for (int o = 8; o > 0; o >>= 1) ss += __shfl_xor_sync(0xffffffffu, ss, o);
            if (i2 == 0) { mus[r] = mu; stds[r] = sqrtf(ss*(1.f/64.f) + 1e-6f); }
        }
        __syncthreads();

        for (int idx = tid; idx < 1024; idx += 256) {
            int r = idx >> 6, cc = idx & 63;
            float xh = (zs[idx] - mus[r]) / stds[r];
            float target = grads[idx] - xks[idx];
            float gxh = (lnw[cc]*xh + lnb[cc] - target) * lnw[cc];
            xhs[idx] = xh;
            zs[idx]  = gxh;
        }
        __syncthreads();

        {
            int r = tid >> 4, i2 = tid & 15;
            float4 g4 = *(const float4*)&zs [r*64 + i2*4];
            float4 x4 = *(const float4*)&xhs[r*64 + i2*4];
            float s1 = g4.x+g4.y+g4.z+g4.w;
            float s2 = g4.x*x4.x + g4.y*x4.y + g4.z*x4.z + g4.w*x4.w;
#pragma unroll
            for (int o = 8; o > 0; o >>= 1) {
                s1 += __shfl_xor_sync(0xffffffffu, s1, o);
                s2 += __shfl_xor_sync(0xffffffffu, s2, o);
            }
            if (i2 == 0) { sg1[r] = s1; sg2[r] = s2; }
        }
        __syncthreads();

        for (int idx = tid; idx < 1024; idx += 256) {
            int r = idx >> 6;
            float gxh = zs[idx];
            grads[idx] = (64.f*gxh - sg1[r] - xhs[idx]*sg2[r]) / (64.f*stds[r]);
        }
        {
            int r = tid >> 4, j = tid & 15;
            float m = 0.f;
            if (j <= r) {
                float d = 0.f;
#pragma unroll 8
                for (int k = 0; k < 64; k++) d += xqs[r*64+k] * xkTs[k*17+j];
                m = etas[j] * (d + 1.f);
            }
            Ms[tid] = m;
        }
        __syncthreads();

        {
            float bb = b1s[c];
            float a0=bb,a1=bb,a2=bb,a3=bb;
#pragma unroll 8
            for (int k = 0; k < 64; k++) {
                float w = W1s[k*64 + c];
                a0 += xqs[(r0+0)*64+k]*w;
                a1 += xqs[(r0+1)*64+k]*w;
                a2 += xqs[(r0+2)*64+k]*w;
                a3 += xqs[(r0+3)*64+k]*w;
            }
#pragma unroll
            for (int j = 0; j < 16; j++) {
                float g = grads[j*64 + c];
                a0 -= Ms[(r0+0)*16+j]*g;
                a1 -= Ms[(r0+1)*16+j]*g;
                a2 -= Ms[(r0+2)*16+j]*g;
                a3 -= Ms[(r0+3)*16+j]*g;
            }
            xhs[(r0+0)*64+c] = a0;
            xhs[(r0+1)*64+c] = a1;
            xhs[(r0+2)*64+c] = a2;
            xhs[(r0+3)*64+c] = a3;
        }
        __syncthreads();

        {
            int r = tid >> 4, i2 = tid & 15;
            float4 v = *(const float4*)&xhs[r*64 + i2*4];
            float s = v.x+v.y+v.z+v.w;
#pragma unroll
            for (int o = 8; o > 0; o >>= 1) s += __shfl_xor_sync(0xffffffffu, s, o);
            float mu = s * (1.f/64.f);
            float dx=v.x-mu, dy=v.y-mu, dz=v.z-mu, dw=v.w-mu;
            float ss = dx*dx+dy*dy+dz*dz+dw*dw;
#pragma unroll
            for (int o = 8; o > 0; o >>= 1) ss += __shfl_xor_sync(0xffffffffu, ss, o);
            if (i2 == 0) { mu2[r] = mu; std2[r] = sqrtf(ss*(1.f/64.f) + 1e-6f); }
        }
        __syncthreads();

        for (int idx = tid; idx < 1024; idx += 256) {
            int r = idx >> 6, cc = idx & 63;
            float z = xhs[idx];
            float o = xqs[idx] + (z - mu2[r])/std2[r]*lnw[cc] + lnb[cc];
            g_y[((size_t)b*Lc + n*Kc + r)*Dc + h*HDc + cc] = o;
            zs[idx] = etas[r] * xks[idx];
        }
        __syncthreads();

        {
            float greg[16];
#pragma unroll
            for (int j = 0; j < 16; j++) greg[j] = grads[j*64 + c];
            if (q4 == 0) {
                float s = 0.f;
#pragma unroll
                for (int j = 0; j < 16; j++) s += etas[j]*greg[j];
                b1s[c] -= s;
            }
#pragma unroll
            for (int kk = 0; kk < 16; kk++) {
                int k = q4*16 + kk;
                float s = 0.f;
#pragma unroll
                for (int j = 0; j < 16; j++) s += zs[j*64 + k] * greg[j];
                W1s[k*64 + c] -= s;
            }
        }
        __syncthreads();
    }
}

// ---------------------------------------------------------------------------
// Post layernorm over D=2048 per token; emits bf16 hi/lo split directly.
// ---------------------------------------------------------------------------
__global__ __launch_bounds__(256) void postnorm_kernel(
    const float* __restrict__ pw, const float* __restrict__ pb)
{
    __shared__ float red[8];
    __shared__ float smu, svar;
    const int row = blockIdx.x, tid = threadIdx.x;
    const int lane = tid & 31, wid = tid >> 5;
    const float* x = g_y + (size_t)row*Dc;

    float v[8];
    *(float4*)(v)   = *(const float4*)&x[tid*8];
    *(float4*)(v+4) = *(const float4*)&x[tid*8+4];

    float s = v[0]+v[1]+v[2]+v[3]+v[4]+v[5]+v[6]+v[7];
#pragma unroll
    for (int o = 16; o > 0; o >>= 1) s += __shfl_xor_sync(0xffffffffu, s, o);
    if (lane == 0) red[wid] = s;
    __syncthreads();
    if (tid == 0) {
        float t = 0.f;
#pragma unroll
        for (int i = 0; i < 8; i++) t += red[i];
        smu = t * (1.f/2048.f);
    }
    __syncthreads();
    float mu = smu;

    float ss = 0.f;
#pragma unroll
    for (int i = 0; i < 8; i++) { float d = v[i]-mu; ss += d*d; }
#pragma unroll
    for (int o = 16; o > 0; o >>= 1) ss += __shfl_xor_sync(0xffffffffu, ss, o);
    if (lane == 0) red[wid] = ss;
    __syncthreads();
    if (tid == 0) {
        float t = 0.f;
#pragma unroll
        for (int i = 0; i < 8; i++) t += red[i];
        svar = t * (1.f/2048.f);
    }
    __syncthreads();
    float rstd = rsqrtf(svar + 1e-6f);

    __nv_bfloat16 hb[8], lb[8];
#pragma unroll
    for (int i = 0; i < 8; i++) {
        int cc = tid*8 + i;
        float y = (v[i]-mu)*rstd*pw[cc] + pb[cc];
        hb[i] = __float2bfloat16_rn(y);
        lb[i] = __float2bfloat16_rn(y - __bfloat162float(hb[i]));
    }
    size_t o = (size_t)row*Dc + tid*8;
    *(uint4*)&g_xnh[o] = *(uint4*)hb;
    *(uint4*)&g_xnl[o] = *(uint4*)lb;
}

// ---------------------------------------------------------------------------
extern "C" void kernel_launch(void* const* d_in, const int* in_sizes, int n_in,
                              void* d_out, int out_size)
{
    (void)in_sizes; (void)n_in; (void)out_size;
    const float* hs    = (const float*)d_in[0];
    const float* wq_w  = (const float*)d_in[1];
    const float* wq_b  = (const float*)d_in[2];
    const float* wk_w  = (const float*)d_in[3];
    const float* wk_b  = (const float*)d_in[4];
    const float* wv_w  = (const float*)d_in[5];
    const float* wv_b  = (const float*)d_in[6];
    const float* wo_w  = (const float*)d_in[7];
    const float* wo_b  = (const float*)d_in[8];
    const float* tnw   = (const float*)d_in[9];
    const float* tnb   = (const float*)d_in[10];
    const float* lr_w  = (const float*)d_in[11];
    const float* lr_b  = (const float*)d_in[12];
    const float* W1    = (const float*)d_in[13];
    const float* b1    = (const float*)d_in[14];
    const float* pnw   = (const float*)d_in[15];
    const float* pnb   = (const float*)d_in[16];

    float *pq, *pk, *pv;
    __nv_bfloat16 *ah, *al, *wqh, *wql, *wkh, *wkl, *wvh, *wvl, *woh, *wol, *xnh, *xnl;
    cudaGetSymbolAddress((void**)&pq,  g_q);
    cudaGetSymbolAddress((void**)&pk,  g_k);
    cudaGetSymbolAddress((void**)&pv,  g_v);
    cudaGetSymbolAddress((void**)&ah,  g_ah);
    cudaGetSymbolAddress((void**)&al,  g_al);
    cudaGetSymbolAddress((void**)&wqh, g_wqh);
    cudaGetSymbolAddress((void**)&wql, g_wql);
    cudaGetSymbolAddress((void**)&wkh, g_wkh);
    cudaGetSymbolAddress((void**)&wkl, g_wkl);
    cudaGetSymbolAddress((void**)&wvh, g_wvh);
    cudaGetSymbolAddress((void**)&wvl, g_wvl);
    cudaGetSymbolAddress((void**)&woh, g_woh);
    cudaGetSymbolAddress((void**)&wol, g_wol);
    cudaGetSymbolAddress((void**)&xnh, g_xnh);
    cudaGetSymbolAddress((void**)&xnl, g_xnl);

    const int nA = Mrows*Dc;     // 16.7M
    const int nW = Dc*Dc;        // 4.2M
    conv_kernel<<<nA/1024, 256>>>(hs,   ah,  al,  nA);
    conv_kernel<<<nW/1024, 256>>>(wq_w, wqh, wql, nW);
    conv_kernel<<<nW/1024, 256>>>(wk_w, wkh, wkl, nW);
    conv_kernel<<<nW/1024, 256>>>(wv_w, wvh, wvl, nW);
    conv_kernel<<<nW/1024, 256>>>(wo_w, woh, wol, nW);

    dim3 gg(Dc/128, Mrows/128);   // (16, 64)
    hgemm_kernel<<<gg, 256>>>(ah, al, wqh, wql, wq_b, pq, 1);
    hgemm_kernel<<<gg, 256>>>(ah, al, wkh, wkl, wk_b, pk, 1);
    hgemm_kernel<<<gg, 256>>>(ah, al, wvh, wvl, wv_b, pv, 1);
    lr_kernel<<<Mrows, 256>>>(hs, lr_w, lr_b);
    norm_kernel<<<(Bb*Hh*NMBc*Kc)/8, 256>>>(tnw, tnb);
    scan_kernel<<<Bb*Hh, 256>>>(W1, b1, tnw, tnb);
    postnorm_kernel<<<Mrows, 256>>>(pnw, pnb);
    hgemm_kernel<<<gg, 256>>>(xnh, xnl, woh, wol, wo_b, (float*)d_out, 0);
}

// round 5
// speedup vs baseline: 1.0383x; 1.0383x over previous
#include <cuda_runtime.h>
#include <cuda_bf16.h>
#include <math.h>
#include <stdint.h>

// Problem constants (fixed shapes)
constexpr int Bb  = 2;
constexpr int Lc  = 4096;
constexpr int Dc  = 2048;
constexpr int Hh  = 32;
constexpr int Kc  = 16;
constexpr int HDc = 64;
constexpr int NMBc = 256;           // L / K
constexpr int Mrows = Bb * Lc;      // 8192

// Scratch (device globals; allocation in kernel_launch is forbidden)
__device__ float g_q  [(size_t)Bb*Hh*NMBc*Kc*HDc];   // scan layout [b][h][n][k][d]
__device__ float g_k  [(size_t)Bb*Hh*NMBc*Kc*HDc];
__device__ float g_v  [(size_t)Bb*Hh*NMBc*Kc*HDc];
__device__ float g_eta[(size_t)Bb*Hh*NMBc*Kc];
__device__ float g_y  [(size_t)Bb*Lc*Dc];            // scan output, token layout

// bf16 hi/lo split operands for tensor-core GEMMs
__device__ __nv_bfloat16 g_ah [(size_t)Mrows*Dc];
__device__ __nv_bfloat16 g_al [(size_t)Mrows*Dc];
__device__ __nv_bfloat16 g_wqh[(size_t)Dc*Dc];
__device__ __nv_bfloat16 g_wql[(size_t)Dc*Dc];
__device__ __nv_bfloat16 g_wkh[(size_t)Dc*Dc];
__device__ __nv_bfloat16 g_wkl[(size_t)Dc*Dc];
__device__ __nv_bfloat16 g_wvh[(size_t)Dc*Dc];
__device__ __nv_bfloat16 g_wvl[(size_t)Dc*Dc];
__device__ __nv_bfloat16 g_woh[(size_t)Dc*Dc];
__device__ __nv_bfloat16 g_wol[(size_t)Dc*Dc];
__device__ __nv_bfloat16 g_xnh[(size_t)Mrows*Dc];
__device__ __nv_bfloat16 g_xnl[(size_t)Mrows*Dc];

// ---------------------------------------------------------------------------
// fp32 -> bf16 (hi, lo) split conversion.  n must be a multiple of 1024.
// ---------------------------------------------------------------------------
__global__ __launch_bounds__(256) void conv_kernel(
    const float* __restrict__ x, __nv_bfloat16* __restrict__ hi,
    __nv_bfloat16* __restrict__ lo, int n)
{
    int i = (blockIdx.x*256 + threadIdx.x)*4;
    if (i >= n) return;
    float4 v = *(const float4*)&x[i];
    __nv_bfloat16 h[4], l[4];
    float vv[4] = {v.x, v.y, v.z, v.w};
#pragma unroll
    for (int j = 0; j < 4; j++) {
        h[j] = __float2bfloat16_rn(vv[j]);
        l[j] = __float2bfloat16_rn(vv[j] - __bfloat162float(h[j]));
    }
    *(uint2*)&hi[i] = *(uint2*)h;
    *(uint2*)&lo[i] = *(uint2*)l;
}

// ---------------------------------------------------------------------------
// Tensor-core GEMM: C(8192x2048) = (Ah+Al)(8192x2048) @ (Bh+Bl)(2048x2048) + bias
// 3-pass bf16 split: Ah@Bh + Ah@Bl + Al@Bh  (error ~2^-18 per element)
// mode 0: row-major C; mode 1: permute into scan layout [b][h][n][k][d]
// CTA tile 128x128, BK=16, 4-stage cp.async pipeline, 8 warps of 64x32.
// ---------------------------------------------------------------------------
#define LDSM4(R, addr) asm volatile( \
    "ldmatrix.sync.aligned.m8n8.x4.shared.b16 {%0,%1,%2,%3}, [%4];\n" \
    : "=r"((R)[0]), "=r"((R)[1]), "=r"((R)[2]), "=r"((R)[3]) : "r"(addr))
#define LDSM4T(R, addr) asm volatile( \
    "ldmatrix.sync.aligned.m8n8.x4.trans.shared.b16 {%0,%1,%2,%3}, [%4];\n" \
    : "=r"((R)[0]), "=r"((R)[1]), "=r"((R)[2]), "=r"((R)[3]) : "r"(addr))
#define MMA16816(d, a, b0, b1) asm volatile( \
    "mma.sync.aligned.m16n8k16.row.col.f32.bf16.bf16.f32 " \
    "{%0,%1,%2,%3},{%4,%5,%6,%7},{%8,%9},{%0,%1,%2,%3};\n" \
    : "+f"((d)[0]), "+f"((d)[1]), "+f"((d)[2]), "+f"((d)[3]) \
    : "r"((a)[0]), "r"((a)[1]), "r"((a)[2]), "r"((a)[3]), "r"(b0), "r"(b1))

__device__ __forceinline__ void cp16(uint32_t dst, const void* src) {
    asm volatile("cp.async.cg.shared.global [%0], [%1], 16;\n" :: "r"(dst), "l"(src));
}

// Region byte offsets in dynamic smem (4 stages x 4096B per region)
constexpr uint32_t R_AH = 0, R_AL = 16384, R_BH = 32768, R_BL = 49152;
constexpr uint32_t HG_SMEM = 65536;

__global__ __launch_bounds__(256, 1) void hgemm_kernel(
    const __nv_bfloat16* __restrict__ Ah, const __nv_bfloat16* __restrict__ Al,
    const __nv_bfloat16* __restrict__ Bh, const __nv_bfloat16* __restrict__ Bl,
    const float* __restrict__ bias, float* __restrict__ C, int mode)
{
    extern __shared__ __align__(16) unsigned char hsm[];
    const int tid = threadIdx.x, lane = tid & 31, wid = tid >> 5;
    const int wm = wid >> 2, wn = wid & 3;
    const int row0 = blockIdx.y*128, col0 = blockIdx.x*128;
    const uint32_t sbase = (uint32_t)__cvta_generic_to_shared(hsm);

    // ---- prefetch (global->smem) thread mapping ----
    const int pr = tid >> 1, pc = tid & 1;        // A: row 0..127, chunk 0..1
    const int pk = tid >> 4, pcb = tid & 15;      // B: k 0..15, chunk 0..15
    const __nv_bfloat16* gAh = Ah + (size_t)(row0+pr)*Dc + pc*8;
    const __nv_bfloat16* gAl = Al + (size_t)(row0+pr)*Dc + pc*8;
    const __nv_bfloat16* gBh = Bh + (size_t)pk*Dc + col0 + pcb*8;
    const __nv_bfloat16* gBl = Bl + (size_t)pk*Dc + col0 + pcb*8;
    const uint32_t aoff = (uint32_t)(pr*16 + 8*(pc ^ ((pr>>2)&1)))*2;   // intra-stage
    const uint32_t boff = (uint32_t)(pk*128 + 8*(pcb ^ (pk&7)))*2;

    // ---- ldmatrix per-lane intra-stage offsets ----
    const int ar = lane & 15, ac = lane >> 4;
    uint32_t adA[4];
#pragma unroll
    for (int mi = 0; mi < 4; mi++) {
        int r = wm*64 + mi*16 + ar;
        adA[mi] = (uint32_t)(r*16 + 8*(ac ^ ((r>>2)&1)))*2;
    }
    const int bk = (lane & 7) + ((lane >> 3) & 1)*8;
    uint32_t adB[2];
#pragma unroll
    for (int nj = 0; nj < 2; nj++) {
        int c = wn*4 + nj*2 + ((lane >> 4) & 1);
        adB[nj] = (uint32_t)(bk*128 + 8*(c ^ (bk & 7)))*2;
    }

    float acc[4][4][4];
#pragma unroll
    for (int i = 0; i < 4; i++)
#pragma unroll
        for (int j = 0; j < 4; j++)
#pragma unroll
            for (int k = 0; k < 4; k++) acc[i][j][k] = 0.f;

    constexpr int KT = Dc / 16;   // 128

    auto prefetch = [&](int kt) {
        const uint32_t so = (uint32_t)(kt & 3)*4096;
        const size_t gA = (size_t)kt*16;
        const size_t gB = (size_t)kt*16*Dc;
        cp16(sbase + R_AH + so + aoff, gAh + gA);
        cp16(sbase + R_AL + so + aoff, gAl + gA);
        cp16(sbase + R_BH + so + boff, gBh + gB);
        cp16(sbase + R_BL + so + boff, gBl + gB);
        asm volatile("cp.async.commit_group;\n");
    };

    prefetch(0);
    prefetch(1);
    prefetch(2);

    for (int kt = 0; kt < KT; kt++) {
        asm volatile("cp.async.wait_group 2;\n");
        __syncthreads();
        if (kt + 3 < KT) prefetch(kt + 3);
        else asm volatile("cp.async.commit_group;\n");

        const uint32_t so = (uint32_t)(kt & 3)*4096;
        uint32_t ah[4][4], al[4][4], bh[2][4], bl[2][4];
#pragma unroll
        for (int mi = 0; mi < 4; mi++) {
            LDSM4(ah[mi], sbase + R_AH + so + adA[mi]);
            LDSM4(al[mi], sbase + R_AL + so + adA[mi]);
        }
#pragma unroll
        for (int nj = 0; nj < 2; nj++) {
            LDSM4T(bh[nj], sbase + R_BH + so + adB[nj]);
            LDSM4T(bl[nj], sbase + R_BL + so + adB[nj]);
        }
#pragma unroll
        for (int mi = 0; mi < 4; mi++) {
#pragma unroll
            for (int ni = 0; ni < 4; ni++) {
                const int q = ni >> 1, hb = (ni & 1)*2;
                MMA16816(acc[mi][ni], ah[mi], bh[q][hb], bh[q][hb+1]);
                MMA16816(acc[mi][ni], ah[mi], bl[q][hb], bl[q][hb+1]);
                MMA16816(acc[mi][ni], al[mi], bh[q][hb], bh[q][hb+1]);
            }
        }
    }

    // ---- epilogue ----
    const int g = lane >> 2, t2 = (lane & 3)*2;
#pragma unroll
    for (int mi = 0; mi < 4; mi++) {
        const int r1 = row0 + wm*64 + mi*16 + g;
        const int r2 = r1 + 8;
#pragma unroll
        for (int ni = 0; ni < 4; ni++) {
            const int col = col0 + wn*32 + ni*8 + t2;
            const float2 bv = *(const float2*)&bias[col];
            float2 v0 = make_float2(acc[mi][ni][0] + bv.x, acc[mi][ni][1] + bv.y);
            float2 v1 = make_float2(acc[mi][ni][2] + bv.x, acc[mi][ni][3] + bv.y);
            if (mode == 0) {
                *(float2*)&C[(size_t)r1*Dc + col] = v0;
                *(float2*)&C[(size_t)r2*Dc + col] = v1;
            } else {
                const int h = col >> 6, d = col & 63;
                {
                    int b = r1 >> 12, l = r1 & 4095, n = l >> 4, kk = l & 15;
                    size_t o = ((((size_t)(b*Hh + h))*NMBc + n)*Kc + kk)*HDc + d;
                    *(float2*)&C[o] = v0;
                }
                {
                    int b = r2 >> 12, l = r2 & 4095, n = l >> 4, kk = l & 15;
                    size_t o = ((((size_t)(b*Hh + h))*NMBc + n)*Kc + kk)*HDc + d;
                    *(float2*)&C[o] = v1;
                }
            }
        }
    }
}

// ---------------------------------------------------------------------------
// lr GEMM: eta[t][h] = sigmoid(hs[t] . lr_w[h] + lr_b[h]) / 1024
// Tile: 64 tokens x 32 heads per CTA, fp32, K-chunks of 32.
// ---------------------------------------------------------------------------
__global__ __launch_bounds__(256) void lr_gemm_kernel(
    const float* __restrict__ hs, const float* __restrict__ lr_w,
    const float* __restrict__ lr_b)
{
    __shared__ float As[32][65];   // [k][token]
    __shared__ float Ws[32][32];   // [k][head]
    const int tid = threadIdx.x;
    const int t0 = blockIdx.x*64;
    const int r0 = (tid >> 4)*4;        // 4 tokens
    const int c0 = (tid & 15)*2;        // 2 heads

    float acc[4][2];
#pragma unroll
    for (int i = 0; i < 4; i++) { acc[i][0] = 0.f; acc[i][1] = 0.f; }

    const int lrow = tid >> 2;              // 0..63
    const int lcol = (tid & 3)*8;           // 0,8,16,24

    for (int k0 = 0; k0 < Dc; k0 += 32) {
        // load A tile transposed
        float4 a0 = *(const float4*)&hs[(size_t)(t0+lrow)*Dc + k0 + lcol];
        float4 a1 = *(const float4*)&hs[(size_t)(t0+lrow)*Dc + k0 + lcol + 4];
        // load W tile
        float wv[4];
#pragma unroll
        for (int j = 0; j < 4; j++) {
            int i = tid + j*256;            // 0..1023
            int h = i >> 5, k = i & 31;
            wv[j] = lr_w[(size_t)h*Dc + k0 + k];
        }
        __syncthreads();
        As[lcol+0][lrow] = a0.x; As[lcol+1][lrow] = a0.y;
        As[lcol+2][lrow] = a0.z; As[lcol+3][lrow] = a0.w;
        As[lcol+4][lrow] = a1.x; As[lcol+5][lrow] = a1.y;
        As[lcol+6][lrow] = a1.z; As[lcol+7][lrow] = a1.w;
#pragma unroll
        for (int j = 0; j < 4; j++) {
            int i = tid + j*256;
            Ws[i & 31][i >> 5] = wv[j];
        }
        __syncthreads();
#pragma unroll 8
        for (int k = 0; k < 32; k++) {
            float w0 = Ws[k][c0], w1 = Ws[k][c0+1];
#pragma unroll
            for (int i = 0; i < 4; i++) {
                float a = As[k][r0+i];
                acc[i][0] += a*w0;
                acc[i][1] += a*w1;
            }
        }
    }

#pragma unroll
    for (int i = 0; i < 4; i++) {
        const int t = t0 + r0 + i;
        const int b = t >> 12, l = t & 4095, n = l >> 4, kk = l & 15;
#pragma unroll
        for (int j = 0; j < 2; j++) {
            const int h = c0 + j;
            float x = acc[i][j] + lr_b[h];
            float sig = 1.f/(1.f+expf(-x));
            g_eta[(((size_t)(b*Hh + h))*NMBc + n)*Kc + kk] = sig * (1.f/1024.f);
        }
    }
}

// ---------------------------------------------------------------------------
// Per (token, head): L2-normalize Q,K; XV <- w*((v-k)-mu)/(std+1e-8)+b+k
// ---------------------------------------------------------------------------
__global__ __launch_bounds__(256) void norm_kernel(
    const float* __restrict__ tnw, const float* __restrict__ tnb)
{
    const int wg   = blockIdx.x*8 + (threadIdx.x >> 5);
    const int lane = threadIdx.x & 31;
    const size_t base = (size_t)wg * 64;
    const int h = (wg >> 12) & 31;

    float q0 = g_q[base+lane], q1 = g_q[base+lane+32];
    float k0 = g_k[base+lane], k1 = g_k[base+lane+32];
    float v0 = g_v[base+lane], v1 = g_v[base+lane+32];

    float s = q0*q0 + q1*q1;
#pragma unroll
    for (int o = 16; o > 0; o >>= 1) s += __shfl_xor_sync(0xffffffffu, s, o);
    float inv = 1.f / fmaxf(sqrtf(s), 1e-12f);
    q0 *= inv; q1 *= inv;

    s = k0*k0 + k1*k1;
#pragma unroll
    for (int o = 16; o > 0; o >>= 1) s += __shfl_xor_sync(0xffffffffu, s, o);
    inv = 1.f / fmaxf(sqrtf(s), 1e-12f);
    k0 *= inv; k1 *= inv;

    float d0 = v0 - k0, d1 = v1 - k1;
    s = d0 + d1;
#pragma unroll
    for (int o = 16; o > 0; o >>= 1) s += __shfl_xor_sync(0xffffffffu, s, o);
    float mu = s * (1.f/64.f);
    float e0 = d0 - mu, e1 = d1 - mu;
    s = e0*e0 + e1*e1;
#pragma unroll
    for (int o = 16; o > 0; o >>= 1) s += __shfl_xor_sync(0xffffffffu, s, o);
    float stdv = sqrtf(s * (1.f/63.f));       // ddof=1
    float den = stdv + 1e-8f;

    float w0 = tnw[h*64+lane], w1 = tnw[h*64+lane+32];
    float b0 = tnb[h*64+lane], b1v = tnb[h*64+lane+32];
    float nv0 = w0*(e0/den) + b0  + k0;
    float nv1 = w1*(e1/den) + b1v + k1;

    g_q[base+lane] = q0; g_q[base+lane+32] = q1;
    g_k[base+lane] = k0; g_k[base+lane+32] = k1;
    g_v[base+lane] = nv0; g_v[base+lane+32] = nv1;
}

// ---------------------------------------------------------------------------
// Sequential TTT scan. One CTA per (b,h). 256 threads.
// Tile n+1 is prefetched into registers at iteration start and committed to
// shared at iteration end (hides global-load latency).
// ---------------------------------------------------------------------------
__global__ __launch_bounds__(256) void scan_kernel(
    const float* __restrict__ W1g, const float* __restrict__ b1g,
    const float* __restrict__ tnw, const float* __restrict__ tnb)
{
    __shared__ __align__(16) float W1s[64*64];
    __shared__ __align__(16) float xqs[1024];
    __shared__ __align__(16) float xks[1024];
    __shared__ __align__(16) float xvs[1024];
    __shared__ __align__(16) float grads[1024];
    __shared__ __align__(16) float zs[1024];
    __shared__ __align__(16) float xhs[1024];
    __shared__ __align__(16) float xkTs[64*17];
    __shared__ __align__(16) float Ms[256];
    __shared__ float b1s[64], lnw[64], lnb[64], etas[16];
    __shared__ float mus[16], stds[16], sg1[16], sg2[16], mu2[16], std2[16];

    const int bh = blockIdx.x;
    const int b = bh >> 5, h = bh & 31;
    const int tid = threadIdx.x;
    const int c = tid & 63, q4 = tid >> 6;
    const int r0 = q4 * 4;

    for (int i = tid; i < 4096; i += 256) W1s[i] = W1g[(size_t)h*4096 + i];
    if (tid < 64) {
        b1s[tid] = b1g[h*64 + tid];
        lnw[tid] = tnw[h*64 + tid];
        lnb[tid] = tnb[h*64 + tid];
    }

    const size_t tile0 = (size_t)bh * (NMBc * 1024);

    // prologue: tile 0 into smem
    for (int j = 0; j < 4; j++) {
        int idx = tid + j*256;
        float vq = g_q[tile0+idx];
        float vk = g_k[tile0+idx];
        float vv = g_v[tile0+idx];
        xqs[idx] = vq; xks[idx] = vk; xvs[idx] = vv;
        xkTs[(idx & 63)*17 + (idx >> 6)] = vk;
    }
    if (tid < 16) etas[tid] = g_eta[(size_t)bh*NMBc*Kc + tid];
    __syncthreads();

    for (int n = 0; n < NMBc; n++) {
        // ---- register prefetch of tile n+1 ----
        float rq[4], rk[4], rv[4], re = 0.f;
        const bool pf = (n + 1 < NMBc);
        if (pf) {
            const size_t tb = tile0 + (size_t)(n+1)*1024;
#pragma unroll
            for (int j = 0; j < 4; j++) {
                rq[j] = g_q[tb + tid + j*256];
                rk[j] = g_k[tb + tid + j*256];
                rv[j] = g_v[tb + tid + j*256];
            }
            if (tid < 16) re = g_eta[((size_t)bh*NMBc + n+1)*Kc + tid];
        }

        // ---- Z1 = xk @ W1 + b1 ----
        {
            float a0=0.f,a1=0.f,a2=0.f,a3=0.f;
#pragma unroll 8
            for (int k = 0; k < 64; k++) {
                float w = W1s[k*64 + c];
                a0 += xks[(r0+0)*64+k]*w;
                a1 += xks[(r0+1)*64+k]*w;
                a2 += xks[(r0+2)*64+k]*w;
                a3 += xks[(r0+3)*64+k]*w;
            }
            float bb = b1s[c];
            zs[(r0+0)*64+c] = a0+bb;
            zs[(r0+1)*64+c] = a1+bb;
            zs[(r0+2)*64+c] = a2+bb;
            zs[(r0+3)*64+c] = a3+bb;
        }
        __syncthreads();

        // ---- row stats of Z1 ----
        {
            int r = tid >> 4, i2 = tid & 15;
            float4 v = *(const float4*)&zs[r*64 + i2*4];
            float s = v.x+v.y+v.z+v.w;
#pragma unroll
            for (int o = 8; o > 0; o >>= 1) s += __shfl_xor_sync(0xffffffffu, s, o);
            float mu = s * (1.f/64.f);
            float dx=v.x-mu, dy=v.y-mu, dz=v.z-mu, dw=v.w-mu;
            float ss = dx*dx+dy*dy+dz*dz+dw*dw;
#pragma unroll
            for (int o = 8; o > 0; o >>= 1) ss += __shfl_xor_sync(0xffffffffu, ss, o);
            if (i2 == 0) { mus[r] = mu; stds[r] = sqrtf(ss*(1.f/64.f) + 1e-6f); }
        }
        __syncthreads();

        // ---- x_hat + grad_x_hat ----
        for (int j = 0; j < 4; j++) {
            int idx = tid + j*256;
            int r = idx >> 6, cc = idx & 63;
            float xh = (zs[idx] - mus[r]) / stds[r];
            float target = xvs[idx] - xks[idx];
            float gxh = (lnw[cc]*xh + lnb[cc] - target) * lnw[cc];
            xhs[idx] = xh;
            zs[idx]  = gxh;
        }
        __syncthreads();

        // ---- row sums: sum(gxh), sum(xh*gxh) ----
        {
            int r = tid >> 4, i2 = tid & 15;
            float4 g4 = *(const float4*)&zs [r*64 + i2*4];
            float4 x4 = *(const float4*)&xhs[r*64 + i2*4];
            float s1 = g4.x+g4.y+g4.z+g4.w;
            float s2 = g4.x*x4.x + g4.y*x4.y + g4.z*x4.z + g4.w*x4.w;
#pragma unroll
            for (int o = 8; o > 0; o >>= 1) {
                s1 += __shfl_xor_sync(0xffffffffu, s1, o);
                s2 += __shfl_xor_sync(0xffffffffu, s2, o);
            }
            if (i2 == 0) { sg1[r] = s1; sg2[r] = s2; }
        }
        __syncthreads();

        // ---- grad ----
        for (int j = 0; j < 4; j++) {
            int idx = tid + j*256;
            int r = idx >> 6;
            float gxh = zs[idx];
            grads[idx] = (64.f*gxh - sg1[r] - xhs[idx]*sg2[r]) / (64.f*stds[r]);
        }
        // ---- M[r][j] = eta[j]*(Attn[r][j]+1) for j<=r ----
        {
            int r = tid >> 4, j = tid & 15;
            float m = 0.f;
            if (j <= r) {
                float d = 0.f;
#pragma unroll 8
                for (int k = 0; k < 64; k++) d += xqs[r*64+k] * xkTs[k*17+j];
                m = etas[j] * (d + 1.f);
            }
            Ms[tid] = m;
        }
        __syncthreads();

        // ---- Z1_bar = xq @ W1 + b1 - M @ grad ----
        {
            float bb = b1s[c];
            float a0=bb,a1=bb,a2=bb,a3=bb;
#pragma unroll 8
            for (int k = 0; k < 64; k++) {
                float w = W1s[k*64 + c];
                a0 += xqs[(r0+0)*64+k]*w;
                a1 += xqs[(r0+1)*64+k]*w;
                a2 += xqs[(r0+2)*64+k]*w;
                a3 += xqs[(r0+3)*64+k]*w;
            }
#pragma unroll
            for (int j = 0; j < 16; j++) {
                float g = grads[j*64 + c];
                a0 -= Ms[(r0+0)*16+j]*g;
                a1 -= Ms[(r0+1)*16+j]*g;
                a2 -= Ms[(r0+2)*16+j]*g;
                a3 -= Ms[(r0+3)*16+j]*g;
            }
            xhs[(r0+0)*64+c] = a0;
            xhs[(r0+1)*64+c] = a1;
            xhs[(r0+2)*64+c] = a2;
            xhs[(r0+3)*64+c] = a3;
        }
        __syncthreads();

        // ---- row stats of Z1_bar ----
        {
            int r = tid >> 4, i2 = tid & 15;
            float4 v = *(const float4*)&xhs[r*64 + i2*4];
            float s = v.x+v.y+v.z+v.w;
#pragma unroll
            for (int o = 8; o > 0; o >>= 1) s += __shfl_xor_sync(0xffffffffu, s, o);
            float mu = s * (1.f/64.f);
            float dx=v.x-mu, dy=v.y-mu, dz=v.z-mu, dw=v.w-mu;
            float ss = dx*dx+dy*dy+dz*dz+dw*dw;
#pragma unroll
            for (int o = 8; o > 0; o >>= 1) ss += __shfl_xor_sync(0xffffffffu, ss, o);
            if (i2 == 0) { mu2[r] = mu; std2[r] = sqrtf(ss*(1.f/64.f) + 1e-6f); }
        }
        __syncthreads();

        // ---- output write; exk = eta[r]*xk into zs ----
        for (int j = 0; j < 4; j++) {
            int idx = tid + j*256;
            int r = idx >> 6, cc = idx & 63;
            float z = xhs[idx];
            float o = xqs[idx] + (z - mu2[r])/std2[r]*lnw[cc] + lnb[cc];
            g_y[((size_t)b*Lc + n*Kc + r)*Dc + h*HDc + cc] = o;
            zs[idx] = etas[r] * xks[idx];
        }
        __syncthreads();

        // ---- state update ----
        {
            float greg[16];
#pragma unroll
            for (int j = 0; j < 16; j++) greg[j] = grads[j*64 + c];
            if (q4 == 0) {
                float s = 0.f;
#pragma unroll
                for (int j = 0; j < 16; j++) s += etas[j]*greg[j];
                b1s[c] -= s;
            }
#pragma unroll
            for (int kk = 0; kk < 16; kk++) {
                int k = q4*16 + kk;
                float s = 0.f;
#pragma unroll
                for (int j = 0; j < 16; j++) s += zs[j*64 + k] * greg[j];
                W1s[k*64 + c] -= s;
            }
        }
        __syncthreads();

        // ---- commit prefetched tile n+1 ----
        if (pf) {
#pragma unroll
            for (int j = 0; j < 4; j++) {
                int idx = tid + j*256;
                xqs[idx] = rq[j];
                xks[idx] = rk[j];
                xvs[idx] = rv[j];
                xkTs[(idx & 63)*17 + (idx >> 6)] = rk[j];
            }
            if (tid < 16) etas[tid] = re;
        }
        __syncthreads();
    }
}

// ---------------------------------------------------------------------------
// Post layernorm over D=2048 per token; emits bf16 hi/lo split directly.
// ---------------------------------------------------------------------------
__global__ __launch_bounds__(256) void postnorm_kernel(
    const float* __restrict__ pw, const float* __restrict__ pb)
{
    __shared__ float red[8];
    __shared__ float smu, svar;
    const int row = blockIdx.x, tid = threadIdx.x;
    const int lane = tid & 31, wid = tid >> 5;
    const float* x = g_y + (size_t)row*Dc;

    float v[8];
    *(float4*)(v)   = *(const float4*)&x[tid*8];
    *(float4*)(v+4) = *(const float4*)&x[tid*8+4];

    float s = v[0]+v[1]+v[2]+v[3]+v[4]+v[5]+v[6]+v[7];
#pragma unroll
    for (int o = 16; o > 0; o >>= 1) s += __shfl_xor_sync(0xffffffffu, s, o);
    if (lane == 0) red[wid] = s;
    __syncthreads();
    if (tid == 0) {
        float t = 0.f;
#pragma unroll
        for (int i = 0; i < 8; i++) t += red[i];
        smu = t * (1.f/2048.f);
    }
    __syncthreads();
    float mu = smu;

    float ss = 0.f;
#pragma unroll
    for (int i = 0; i < 8; i++) { float d = v[i]-mu; ss += d*d; }
#pragma unroll
    for (int o = 16; o > 0; o >>= 1) ss += __shfl_xor_sync(0xffffffffu, ss, o);
    if (lane == 0) red[wid] = ss;
    __syncthreads();
    if (tid == 0) {
        float t = 0.f;
#pragma unroll
        for (int i = 0; i < 8; i++) t += red[i];
        svar = t * (1.f/2048.f);
    }
    __syncthreads();
    float rstd = rsqrtf(svar + 1e-6f);

    __nv_bfloat16 hb[8], lb[8];
#pragma unroll
    for (int i = 0; i < 8; i++) {
        int cc = tid*8 + i;
        float y = (v[i]-mu)*rstd*pw[cc] + pb[cc];
        hb[i] = __float2bfloat16_rn(y);
        lb[i] = __float2bfloat16_rn(y - __bfloat162float(hb[i]));
    }
    size_t o = (size_t)row*Dc + tid*8;
    *(uint4*)&g_xnh[o] = *(uint4*)hb;
    *(uint4*)&g_xnl[o] = *(uint4*)lb;
}

// ---------------------------------------------------------------------------
extern "C" void kernel_launch(void* const* d_in, const int* in_sizes, int n_in,
                              void* d_out, int out_size)
{
    (void)in_sizes; (void)n_in; (void)out_size;
    const float* hs    = (const float*)d_in[0];
    const float* wq_w  = (const float*)d_in[1];
    const float* wq_b  = (const float*)d_in[2];
    const float* wk_w  = (const float*)d_in[3];
    const float* wk_b  = (const float*)d_in[4];
    const float* wv_w  = (const float*)d_in[5];
    const float* wv_b  = (const float*)d_in[6];
    const float* wo_w  = (const float*)d_in[7];
    const float* wo_b  = (const float*)d_in[8];
    const float* tnw   = (const float*)d_in[9];
    const float* tnb   = (const float*)d_in[10];
    const float* lr_w  = (const float*)d_in[11];
    const float* lr_b  = (const float*)d_in[12];
    const float* W1    = (const float*)d_in[13];
    const float* b1    = (const float*)d_in[14];
    const float* pnw   = (const float*)d_in[15];
    const float* pnb   = (const float*)d_in[16];

    float *pq, *pk, *pv;
    __nv_bfloat16 *ah, *al, *wqh, *wql, *wkh, *wkl, *wvh, *wvl, *woh, *wol, *xnh, *xnl;
    cudaGetSymbolAddress((void**)&pq,  g_q);
    cudaGetSymbolAddress((void**)&pk,  g_k);
    cudaGetSymbolAddress((void**)&pv,  g_v);
    cudaGetSymbolAddress((void**)&ah,  g_ah);
    cudaGetSymbolAddress((void**)&al,  g_al);
    cudaGetSymbolAddress((void**)&wqh, g_wqh);
    cudaGetSymbolAddress((void**)&wql, g_wql);
    cudaGetSymbolAddress((void**)&wkh, g_wkh);
    cudaGetSymbolAddress((void**)&wkl, g_wkl);
    cudaGetSymbolAddress((void**)&wvh, g_wvh);
    cudaGetSymbolAddress((void**)&wvl, g_wvl);
    cudaGetSymbolAddress((void**)&woh, g_woh);
    cudaGetSymbolAddress((void**)&wol, g_wol);
    cudaGetSymbolAddress((void**)&xnh, g_xnh);
    cudaGetSymbolAddress((void**)&xnl, g_xnl);

    cudaFuncSetAttribute(hgemm_kernel,
                         cudaFuncAttributeMaxDynamicSharedMemorySize, HG_SMEM);

    const int nA = Mrows*Dc;     // 16.7M
    const int nW = Dc*Dc;        // 4.2M
    conv_kernel<<<nA/1024, 256>>>(hs,   ah,  al,  nA);
    conv_kernel<<<nW/1024, 256>>>(wq_w, wqh, wql, nW);
    conv_kernel<<<nW/1024, 256>>>(wk_w, wkh, wkl, nW);
    conv_kernel<<<nW/1024, 256>>>(wv_w, wvh, wvl, nW);
    conv_kernel<<<nW/1024, 256>>>(wo_w, woh, wol, nW);

    dim3 gg(Dc/128, Mrows/128);   // (16, 64)
    hgemm_kernel<<<gg, 256, HG_SMEM>>>(ah, al, wqh, wql, wq_b, pq, 1);
    hgemm_kernel<<<gg, 256, HG_SMEM>>>(ah, al, wkh, wkl, wk_b, pk, 1);
    hgemm_kernel<<<gg, 256, HG_SMEM>>>(ah, al, wvh, wvl, wv_b, pv, 1);
    lr_gemm_kernel<<<Mrows/64, 256>>>(hs, lr_w, lr_b);
    norm_kernel<<<(Bb*Hh*NMBc*Kc)/8, 256>>>(tnw, tnb);
    scan_kernel<<<Bb*Hh, 256>>>(W1, b1, tnw, tnb);
    postnorm_kernel<<<Mrows, 256>>>(pnw, pnb);
    hgemm_kernel<<<gg, 256, HG_SMEM>>>(xnh, xnl, woh, wol, wo_b, (float*)d_out, 0);
}

// round 6
// speedup vs baseline: 1.4887x; 1.4337x over previous
#include <cuda_runtime.h>
#include <cuda_fp16.h>
#include <math.h>
#include <stdint.h>

// Problem constants (fixed shapes)
constexpr int Bb  = 2;
constexpr int Lc  = 4096;
constexpr int Dc  = 2048;
constexpr int Hh  = 32;
constexpr int Kc  = 16;
constexpr int HDc = 64;
constexpr int NMBc = 256;           // L / K
constexpr int Mrows = Bb * Lc;      // 8192

// Scratch (device globals; allocation in kernel_launch is forbidden)
__device__ float g_q  [(size_t)Bb*Hh*NMBc*Kc*HDc];   // scan layout [b][h][n][k][d]
__device__ float g_k  [(size_t)Bb*Hh*NMBc*Kc*HDc];
__device__ float g_v  [(size_t)Bb*Hh*NMBc*Kc*HDc];
__device__ float g_eta[(size_t)Bb*Hh*NMBc*Kc];
__device__ float g_y  [(size_t)Bb*Lc*Dc];            // scan output, token layout

// fp16 operands for tensor-core GEMMs (A: hi only; W: hi/lo split)
__device__ __half g_ah [(size_t)Mrows*Dc];
__device__ __half g_wqh[(size_t)Dc*Dc];
__device__ __half g_wql[(size_t)Dc*Dc];
__device__ __half g_wkh[(size_t)Dc*Dc];
__device__ __half g_wkl[(size_t)Dc*Dc];
__device__ __half g_wvh[(size_t)Dc*Dc];
__device__ __half g_wvl[(size_t)Dc*Dc];
__device__ __half g_woh[(size_t)Dc*Dc];
__device__ __half g_wol[(size_t)Dc*Dc];
__device__ __half g_xnh[(size_t)Mrows*Dc];

// ---------------------------------------------------------------------------
// fp32 -> fp16 (hi only).  n multiple of 1024.
// ---------------------------------------------------------------------------
__global__ __launch_bounds__(256) void conv_hi_kernel(
    const float* __restrict__ x, __half* __restrict__ hi, int n)
{
    int i = (blockIdx.x*256 + threadIdx.x)*4;
    if (i >= n) return;
    float4 v = *(const float4*)&x[i];
    __half h[4];
    h[0] = __float2half_rn(v.x); h[1] = __float2half_rn(v.y);
    h[2] = __float2half_rn(v.z); h[3] = __float2half_rn(v.w);
    *(uint2*)&hi[i] = *(uint2*)h;
}

// ---------------------------------------------------------------------------
// fp32 -> fp16 (hi, lo) split.  n multiple of 1024.
// ---------------------------------------------------------------------------
__global__ __launch_bounds__(256) void conv_hilo_kernel(
    const float* __restrict__ x, __half* __restrict__ hi,
    __half* __restrict__ lo, int n)
{
    int i = (blockIdx.x*256 + threadIdx.x)*4;
    if (i >= n) return;
    float4 v = *(const float4*)&x[i];
    float vv[4] = {v.x, v.y, v.z, v.w};
    __half h[4], l[4];
#pragma unroll
    for (int j = 0; j < 4; j++) {
        h[j] = __float2half_rn(vv[j]);
        l[j] = __float2half_rn(vv[j] - __half2float(h[j]));
    }
    *(uint2*)&hi[i] = *(uint2*)h;
    *(uint2*)&lo[i] = *(uint2*)l;
}

// ---------------------------------------------------------------------------
// Tensor-core GEMM: C(8192x2048) = Ah(8192x2048) @ (Bh+Bl)(2048x2048) + bias
// 2-pass fp16 split: Ah@Bh + Ah@Bl  (dropped A-lo term ~2^-11)
// mode 0: row-major C; mode 1: permute into scan layout [b][h][n][k][d]
// CTA tile 128x128, BK=16, 4-stage cp.async, 8 warps of 64x32, 2 CTAs/SM.
// ---------------------------------------------------------------------------
#define LDSM4(R, addr) asm volatile( \
    "ldmatrix.sync.aligned.m8n8.x4.shared.b16 {%0,%1,%2,%3}, [%4];\n" \
    : "=r"((R)[0]), "=r"((R)[1]), "=r"((R)[2]), "=r"((R)[3]) : "r"(addr))
#define LDSM4T(R, addr) asm volatile( \
    "ldmatrix.sync.aligned.m8n8.x4.trans.shared.b16 {%0,%1,%2,%3}, [%4];\n" \
    : "=r"((R)[0]), "=r"((R)[1]), "=r"((R)[2]), "=r"((R)[3]) : "r"(addr))
#define MMA16816H(d, a, b0, b1) asm volatile( \
    "mma.sync.aligned.m16n8k16.row.col.f32.f16.f16.f32 " \
    "{%0,%1,%2,%3},{%4,%5,%6,%7},{%8,%9},{%0,%1,%2,%3};\n" \
    : "+f"((d)[0]), "+f"((d)[1]), "+f"((d)[2]), "+f"((d)[3]) \
    : "r"((a)[0]), "r"((a)[1]), "r"((a)[2]), "r"((a)[3]), "r"(b0), "r"(b1))

__device__ __forceinline__ void cp16(uint32_t dst, const void* src) {
    asm volatile("cp.async.cg.shared.global [%0], [%1], 16;\n" :: "r"(dst), "l"(src));
}

// Region byte offsets in dynamic smem (4 stages x 4096B per region)
constexpr uint32_t R_A = 0, R_BH = 16384, R_BL = 32768;
constexpr uint32_t HG_SMEM = 49152;

__global__ __launch_bounds__(256, 2) void hgemm_kernel(
    const __half* __restrict__ Ah,
    const __half* __restrict__ Bh, const __half* __restrict__ Bl,
    const float* __restrict__ bias, float* __restrict__ C, int mode)
{
    extern __shared__ __align__(16) unsigned char hsm[];
    const int tid = threadIdx.x, lane = tid & 31, wid = tid >> 5;
    const int wm = wid >> 2, wn = wid & 3;
    const int row0 = blockIdx.y*128, col0 = blockIdx.x*128;
    const uint32_t sbase = (uint32_t)__cvta_generic_to_shared(hsm);

    // ---- prefetch (global->smem) thread mapping ----
    const int pr = tid >> 1, pc = tid & 1;        // A: row 0..127, chunk 0..1
    const int pk = tid >> 4, pcb = tid & 15;      // B: k 0..15, chunk 0..15
    const __half* gA  = Ah + (size_t)(row0+pr)*Dc + pc*8;
    const __half* gBh = Bh + (size_t)pk*Dc + col0 + pcb*8;
    const __half* gBl = Bl + (size_t)pk*Dc + col0 + pcb*8;
    const uint32_t aoff = (uint32_t)(pr*16 + 8*(pc ^ ((pr>>2)&1)))*2;   // intra-stage
    const uint32_t boff = (uint32_t)(pk*128 + 8*(pcb ^ (pk&7)))*2;

    // ---- ldmatrix per-lane intra-stage offsets ----
    const int ar4 = lane & 15, ac = lane >> 4;
    uint32_t adA[4];
#pragma unroll
    for (int mi = 0; mi < 4; mi++) {
        int r = wm*64 + mi*16 + ar4;
        adA[mi] = (uint32_t)(r*16 + 8*(ac ^ ((r>>2)&1)))*2;
    }
    const int bk = (lane & 7) + ((lane >> 3) & 1)*8;
    uint32_t adB[2];
#pragma unroll
    for (int nj = 0; nj < 2; nj++) {
        int c = wn*4 + nj*2 + ((lane >> 4) & 1);
        adB[nj] = (uint32_t)(bk*128 + 8*(c ^ (bk & 7)))*2;
    }

    float acc[4][4][4];
#pragma unroll
    for (int i = 0; i < 4; i++)
#pragma unroll
        for (int j = 0; j < 4; j++)
#pragma unroll
            for (int k = 0; k < 4; k++) acc[i][j][k] = 0.f;

    constexpr int KT = Dc / 16;   // 128

    auto prefetch = [&](int kt) {
        const uint32_t so = (uint32_t)(kt & 3)*4096;
        const size_t gAo = (size_t)kt*16;
        const size_t gBo = (size_t)kt*16*Dc;
        cp16(sbase + R_A  + so + aoff, gA  + gAo);
        cp16(sbase + R_BH + so + boff, gBh + gBo);
        cp16(sbase + R_BL + so + boff, gBl + gBo);
        asm volatile("cp.async.commit_group;\n");
    };

    prefetch(0);
    prefetch(1);
    prefetch(2);

    for (int kt = 0; kt < KT; kt++) {
        asm volatile("cp.async.wait_group 2;\n");
        __syncthreads();
        if (kt + 3 < KT) prefetch(kt + 3);
        else asm volatile("cp.async.commit_group;\n");

        const uint32_t so = (uint32_t)(kt & 3)*4096;
        uint32_t ar[4][4], bh[2][4], bl[2][4];
#pragma unroll
        for (int mi = 0; mi < 4; mi++)
            LDSM4(ar[mi], sbase + R_A + so + adA[mi]);
#pragma unroll
        for (int nj = 0; nj < 2; nj++) {
            LDSM4T(bh[nj], sbase + R_BH + so + adB[nj]);
            LDSM4T(bl[nj], sbase + R_BL + so + adB[nj]);
        }
#pragma unroll
        for (int mi = 0; mi < 4; mi++) {
#pragma unroll
            for (int ni = 0; ni < 4; ni++) {
                const int q = ni >> 1, hb = (ni & 1)*2;
                MMA16816H(acc[mi][ni], ar[mi], bh[q][hb], bh[q][hb+1]);
                MMA16816H(acc[mi][ni], ar[mi], bl[q][hb], bl[q][hb+1]);
            }
        }
    }

    // ---- epilogue ----
    const int g = lane >> 2, t2 = (lane & 3)*2;
#pragma unroll
    for (int mi = 0; mi < 4; mi++) {
        const int r1 = row0 + wm*64 + mi*16 + g;
        const int r2 = r1 + 8;
#pragma unroll
        for (int ni = 0; ni < 4; ni++) {
            const int col = col0 + wn*32 + ni*8 + t2;
            const float2 bv = *(const float2*)&bias[col];
            float2 v0 = make_float2(acc[mi][ni][0] + bv.x, acc[mi][ni][1] + bv.y);
            float2 v1 = make_float2(acc[mi][ni][2] + bv.x, acc[mi][ni][3] + bv.y);
            if (mode == 0) {
                *(float2*)&C[(size_t)r1*Dc + col] = v0;
                *(float2*)&C[(size_t)r2*Dc + col] = v1;
            } else {
                const int h = col >> 6, d = col & 63;
                {
                    int b = r1 >> 12, l = r1 & 4095, n = l >> 4, kk = l & 15;
                    size_t o = ((((size_t)(b*Hh + h))*NMBc + n)*Kc + kk)*HDc + d;
                    *(float2*)&C[o] = v0;
                }
                {
                    int b = r2 >> 12, l = r2 & 4095, n = l >> 4, kk = l & 15;
                    size_t o = ((((size_t)(b*Hh + h))*NMBc + n)*Kc + kk)*HDc + d;
                    *(float2*)&C[o] = v1;
                }
            }
        }
    }
}

// ---------------------------------------------------------------------------
// lr GEMM: eta[t][h] = sigmoid(hs[t] . lr_w[h] + lr_b[h]) / 1024
// ---------------------------------------------------------------------------
__global__ __launch_bounds__(256) void lr_gemm_kernel(
    const float* __restrict__ hs, const float* __restrict__ lr_w,
    const float* __restrict__ lr_b)
{
    __shared__ float As[32][65];   // [k][token]
    __shared__ float Ws[32][32];   // [k][head]
    const int tid = threadIdx.x;
    const int t0 = blockIdx.x*64;
    const int r0 = (tid >> 4)*4;        // 4 tokens
    const int c0 = (tid & 15)*2;        // 2 heads

    float acc[4][2];
#pragma unroll
    for (int i = 0; i < 4; i++) { acc[i][0] = 0.f; acc[i][1] = 0.f; }

    const int lrow = tid >> 2;              // 0..63
    const int lcol = (tid & 3)*8;           // 0,8,16,24

    for (int k0 = 0; k0 < Dc; k0 += 32) {
        float4 a0 = *(const float4*)&hs[(size_t)(t0+lrow)*Dc + k0 + lcol];
        float4 a1 = *(const float4*)&hs[(size_t)(t0+lrow)*Dc + k0 + lcol + 4];
        float wv[4];
#pragma unroll
        for (int j = 0; j < 4; j++) {
            int i = tid + j*256;
            int h = i >> 5, k = i & 31;
            wv[j] = lr_w[(size_t)h*Dc + k0 + k];
        }
        __syncthreads();
        As[lcol+0][lrow] = a0.x; As[lcol+1][lrow] = a0.y;
        As[lcol+2][lrow] = a0.z; As[lcol+3][lrow] = a0.w;
        As[lcol+4][lrow] = a1.x; As[lcol+5][lrow] = a1.y;
        As[lcol+6][lrow] = a1.z; As[lcol+7][lrow] = a1.w;
#pragma unroll
        for (int j = 0; j < 4; j++) {
            int i = tid + j*256;
            Ws[i & 31][i >> 5] = wv[j];
        }
        __syncthreads();
#pragma unroll 8
        for (int k = 0; k < 32; k++) {
            float w0 = Ws[k][c0], w1 = Ws[k][c0+1];
#pragma unroll
            for (int i = 0; i < 4; i++) {
                float a = As[k][r0+i];
                acc[i][0] += a*w0;
                acc[i][1] += a*w1;
            }
        }
    }

#pragma unroll
    for (int i = 0; i < 4; i++) {
        const int t = t0 + r0 + i;
        const int b = t >> 12, l = t & 4095, n = l >> 4, kk = l & 15;
#pragma unroll
        for (int j = 0; j < 2; j++) {
            const int h = c0 + j;
            float x = acc[i][j] + lr_b[h];
            float sig = 1.f/(1.f+expf(-x));
            g_eta[(((size_t)(b*Hh + h))*NMBc + n)*Kc + kk] = sig * (1.f/1024.f);
        }
    }
}

// ---------------------------------------------------------------------------
// Per (token, head): L2-normalize Q,K; XV <- w*((v-k)-mu)/(std+1e-8)+b+k
// ---------------------------------------------------------------------------
__global__ __launch_bounds__(256) void norm_kernel(
    const float* __restrict__ tnw, const float* __restrict__ tnb)
{
    const int wg   = blockIdx.x*8 + (threadIdx.x >> 5);
    const int lane = threadIdx.x & 31;
    const size_t base = (size_t)wg * 64;
    const int h = (wg >> 12) & 31;

    float q0 = g_q[base+lane], q1 = g_q[base+lane+32];
    float k0 = g_k[base+lane], k1 = g_k[base+lane+32];
    float v0 = g_v[base+lane], v1 = g_v[base+lane+32];

    float s = q0*q0 + q1*q1;
#pragma unroll
    for (int o = 16; o > 0; o >>= 1) s += __shfl_xor_sync(0xffffffffu, s, o);
    float inv = 1.f / fmaxf(sqrtf(s), 1e-12f);
    q0 *= inv; q1 *= inv;

    s = k0*k0 + k1*k1;
#pragma unroll
    for (int o = 16; o > 0; o >>= 1) s += __shfl_xor_sync(0xffffffffu, s, o);
    inv = 1.f / fmaxf(sqrtf(s), 1e-12f);
    k0 *= inv; k1 *= inv;

    float d0 = v0 - k0, d1 = v1 - k1;
    s = d0 + d1;
#pragma unroll
    for (int o = 16; o > 0; o >>= 1) s += __shfl_xor_sync(0xffffffffu, s, o);
    float mu = s * (1.f/64.f);
    float e0 = d0 - mu, e1 = d1 - mu;
    s = e0*e0 + e1*e1;
#pragma unroll
    for (int o = 16; o > 0; o >>= 1) s += __shfl_xor_sync(0xffffffffu, s, o);
    float stdv = sqrtf(s * (1.f/63.f));       // ddof=1
    float den = stdv + 1e-8f;

    float w0 = tnw[h*64+lane], w1 = tnw[h*64+lane+32];
    float b0 = tnb[h*64+lane], b1v = tnb[h*64+lane+32];
    float nv0 = w0*(e0/den) + b0  + k0;
    float nv1 = w1*(e1/den) + b1v + k1;

    g_q[base+lane] = q0; g_q[base+lane+32] = q1;
    g_k[base+lane] = k0; g_k[base+lane+32] = k1;
    g_v[base+lane] = nv0; g_v[base+lane+32] = nv1;
}

// ---------------------------------------------------------------------------
// Sequential TTT scan. One CTA per (b,h). 256 threads. Register prefetch of
// tile n+1 hides global latency.
// ---------------------------------------------------------------------------
__global__ __launch_bounds__(256) void scan_kernel(
    const float* __restrict__ W1g, const float* __restrict__ b1g,
    const float* __restrict__ tnw, const float* __restrict__ tnb)
{
    __shared__ __align__(16) float W1s[64*64];
    __shared__ __align__(16) float xqs[1024];
    __shared__ __align__(16) float xks[1024];
    __shared__ __align__(16) float xvs[1024];
    __shared__ __align__(16) float grads[1024];
    __shared__ __align__(16) float zs[1024];
    __shared__ __align__(16) float xhs[1024];
    __shared__ __align__(16) float xkTs[64*17];
    __shared__ __align__(16) float Ms[256];
    __shared__ float b1s[64], lnw[64], lnb[64], etas[16];
    __shared__ float mus[16], stds[16], sg1[16], sg2[16], mu2[16], std2[16];

    const int bh = blockIdx.x;
    const int b = bh >> 5, h = bh & 31;
    const int tid = threadIdx.x;
    const int c = tid & 63, q4 = tid >> 6;
    const int r0 = q4 * 4;

    for (int i = tid; i < 4096; i += 256) W1s[i] = W1g[(size_t)h*4096 + i];
    if (tid < 64) {
        b1s[tid] = b1g[h*64 + tid];
        lnw[tid] = tnw[h*64 + tid];
        lnb[tid] = tnb[h*64 + tid];
    }

    const size_t tile0 = (size_t)bh * (NMBc * 1024);

    for (int j = 0; j < 4; j++) {
        int idx = tid + j*256;
        float vq = g_q[tile0+idx];
        float vk = g_k[tile0+idx];
        float vv = g_v[tile0+idx];
        xqs[idx] = vq; xks[idx] = vk; xvs[idx] = vv;
        xkTs[(idx & 63)*17 + (idx >> 6)] = vk;
    }
    if (tid < 16) etas[tid] = g_eta[(size_t)bh*NMBc*Kc + tid];
    __syncthreads();

    for (int n = 0; n < NMBc; n++) {
        float rq[4], rk[4], rv[4], re = 0.f;
        const bool pf = (n + 1 < NMBc);
        if (pf) {
            const size_t tb = tile0 + (size_t)(n+1)*1024;
#pragma unroll
            for (int j = 0; j < 4; j++) {
                rq[j] = g_q[tb + tid + j*256];
                rk[j] = g_k[tb + tid + j*256];
                rv[j] = g_v[tb + tid + j*256];
            }
            if (tid < 16) re = g_eta[((size_t)bh*NMBc + n+1)*Kc + tid];
        }

        // ---- Z1 = xk @ W1 + b1 ----
        {
            float a0=0.f,a1=0.f,a2=0.f,a3=0.f;
#pragma unroll 8
            for (int k = 0; k < 64; k++) {
                float w = W1s[k*64 + c];
                a0 += xks[(r0+0)*64+k]*w;
                a1 += xks[(r0+1)*64+k]*w;
                a2 += xks[(r0+2)*64+k]*w;
                a3 += xks[(r0+3)*64+k]*w;
            }
            float bb = b1s[c];
            zs[(r0+0)*64+c] = a0+bb;
            zs[(r0+1)*64+c] = a1+bb;
            zs[(r0+2)*64+c] = a2+bb;
            zs[(r0+3)*64+c] = a3+bb;
        }
        __syncthreads();

        // ---- row stats of Z1 ----
        {
            int r = tid >> 4, i2 = tid & 15;
            float4 v = *(const float4*)&zs[r*64 + i2*4];
            float s = v.x+v.y+v.z+v.w;
#pragma unroll
            for (int o = 8; o > 0; o >>= 1) s += __shfl_xor_sync(0xffffffffu, s, o);
            float mu = s * (1.f/64.f);
            float dx=v.x-mu, dy=v.y-mu, dz=v.z-mu, dw=v.w-mu;
            float ss = dx*dx+dy*dy+dz*dz+dw*dw;
#pragma unroll
            for (int o = 8; o > 0; o >>= 1) ss += __shfl_xor_sync(0xffffffffu, ss, o);
            if (i2 == 0) { mus[r] = mu; stds[r] = sqrtf(ss*(1.f/64.f) + 1e-6f); }
        }
        __syncthreads();

        // ---- x_hat + grad_x_hat ----
        for (int j = 0; j < 4; j++) {
            int idx = tid + j*256;
            int r = idx >> 6, cc = idx & 63;
            float xh = (zs[idx] - mus[r]) / stds[r];
            float target = xvs[idx] - xks[idx];
            float gxh = (lnw[cc]*xh + lnb[cc] - target) * lnw[cc];
            xhs[idx] = xh;
            zs[idx]  = gxh;
        }
        __syncthreads();

        // ---- row sums: sum(gxh), sum(xh*gxh) ----
        {
            int r = tid >> 4, i2 = tid & 15;
            float4 g4 = *(const float4*)&zs [r*64 + i2*4];
            float4 x4 = *(const float4*)&xhs[r*64 + i2*4];
            float s1 = g4.x+g4.y+g4.z+g4.w;
            float s2 = g4.x*x4.x + g4.y*x4.y + g4.z*x4.z + g4.w*x4.w;
#pragma unroll
            for (int o = 8; o > 0; o >>= 1) {
                s1 += __shfl_xor_sync(0xffffffffu, s1, o);
                s2 += __shfl_xor_sync(0xffffffffu, s2, o);
            }
            if (i2 == 0) { sg1[r] = s1; sg2[r] = s2; }
        }
        __syncthreads();

        // ---- grad ----
        for (int j = 0; j < 4; j++) {
            int idx = tid + j*256;
            int r = idx >> 6;
            float gxh = zs[idx];
            grads[idx] = (64.f*gxh - sg1[r] - xhs[idx]*sg2[r]) / (64.f*stds[r]);
        }
        // ---- M[r][j] = eta[j]*(Attn[r][j]+1) for j<=r ----
        {
            int r = tid >> 4, j = tid & 15;
            float m = 0.f;
            if (j <= r) {
                float d = 0.f;
#pragma unroll 8
                for (int k = 0; k < 64; k++) d += xqs[r*64+k] * xkTs[k*17+j];
                m = etas[j] * (d + 1.f);
            }
            Ms[tid] = m;
        }
        __syncthreads();

        // ---- Z1_bar = xq @ W1 + b1 - M @ grad ----
        {
            float bb = b1s[c];
            float a0=bb,a1=bb,a2=bb,a3=bb;
#pragma unroll 8
            for (int k = 0; k < 64; k++) {
                float w = W1s[k*64 + c];
                a0 += xqs[(r0+0)*64+k]*w;
                a1 += xqs[(r0+1)*64+k]*w;
                a2 += xqs[(r0+2)*64+k]*w;
                a3 += xqs[(r0+3)*64+k]*w;
            }
#pragma unroll
            for (int j = 0; j < 16; j++) {
                float g = grads[j*64 + c];
                a0 -= Ms[(r0+0)*16+j]*g;
                a1 -= Ms[(r0+1)*16+j]*g;
                a2 -= Ms[(r0+2)*16+j]*g;
                a3 -= Ms[(r0+3)*16+j]*g;
            }
            xhs[(r0+0)*64+c] = a0;
            xhs[(r0+1)*64+c] = a1;
            xhs[(r0+2)*64+c] = a2;
            xhs[(r0+3)*64+c] = a3;
        }
        __syncthreads();

        // ---- row stats of Z1_bar ----
        {
            int r = tid >> 4, i2 = tid & 15;
            float4 v = *(const float4*)&xhs[r*64 + i2*4];
            float s = v.x+v.y+v.z+v.w;
#pragma unroll
            for (int o = 8; o > 0; o >>= 1) s += __shfl_xor_sync(0xffffffffu, s, o);
            float mu = s * (1.f/64.f);
            float dx=v.x-mu, dy=v.y-mu, dz=v.z-mu, dw=v.w-mu;
            float ss = dx*dx+dy*dy+dz*dz+dw*dw;
#pragma unroll
            for (int o = 8; o > 0; o >>= 1) ss += __shfl_xor_sync(0xffffffffu, ss, o);
            if (i2 == 0) { mu2[r] = mu; std2[r] = sqrtf(ss*(1.f/64.f) + 1e-6f); }
        }
        __syncthreads();

        // ---- output write; exk = eta[r]*xk into zs ----
        for (int j = 0; j < 4; j++) {
            int idx = tid + j*256;
            int r = idx >> 6, cc = idx & 63;
            float z = xhs[idx];
            float o = xqs[idx] + (z - mu2[r])/std2[r]*lnw[cc] + lnb[cc];
            g_y[((size_t)b*Lc + n*Kc + r)*Dc + h*HDc + cc] = o;
            zs[idx] = etas[r] * xks[idx];
        }
        __syncthreads();

        // ---- state update ----
        {
            float greg[16];
#pragma unroll
            for (int j = 0; j < 16; j++) greg[j] = grads[j*64 + c];
            if (q4 == 0) {
                float s = 0.f;
#pragma unroll
                for (int j = 0; j < 16; j++) s += etas[j]*greg[j];
                b1s[c] -= s;
            }
#pragma unroll
            for (int kk = 0; kk < 16; kk++) {
                int k = q4*16 + kk;
                float s = 0.f;
#pragma unroll
                for (int j = 0; j < 16; j++) s += zs[j*64 + k] * greg[j];
                W1s[k*64 + c] -= s;
            }
        }
        __syncthreads();

        // ---- commit prefetched tile n+1 ----
        if (pf) {
#pragma unroll
            for (int j = 0; j < 4; j++) {
                int idx = tid + j*256;
                xqs[idx] = rq[j];
                xks[idx] = rk[j];
                xvs[idx] = rv[j];
                xkTs[(idx & 63)*17 + (idx >> 6)] = rk[j];
            }
            if (tid < 16) etas[tid] = re;
        }
        __syncthreads();
    }
}

// ---------------------------------------------------------------------------
// Post layernorm over D=2048 per token; emits fp16 hi directly.
// ---------------------------------------------------------------------------
__global__ __launch_bounds__(256) void postnorm_kernel(
    const float* __restrict__ pw, const float* __restrict__ pb)
{
    __shared__ float red[8];
    __shared__ float smu, svar;
    const int row = blockIdx.x, tid = threadIdx.x;
    const int lane = tid & 31, wid = tid >> 5;
    const float* x = g_y + (size_t)row*Dc;

    float v[8];
    *(float4*)(v)   = *(const float4*)&x[tid*8];
    *(float4*)(v+4) = *(const float4*)&x[tid*8+4];

    float s = v[0]+v[1]+v[2]+v[3]+v[4]+v[5]+v[6]+v[7];
#pragma unroll
    for (int o = 16; o > 0; o >>= 1) s += __shfl_xor_sync(0xffffffffu, s, o);
    if (lane == 0) red[wid] = s;
    __syncthreads();
    if (tid == 0) {
        float t = 0.f;
#pragma unroll
        for (int i = 0; i < 8; i++) t += red[i];
        smu = t * (1.f/2048.f);
    }
    __syncthreads();
    float mu = smu;

    float ss = 0.f;
#pragma unroll
    for (int i = 0; i < 8; i++) { float d = v[i]-mu; ss += d*d; }
#pragma unroll
    for (int o = 16; o > 0; o >>= 1) ss += __shfl_xor_sync(0xffffffffu, ss, o);
    if (lane == 0) red[wid] = ss;
    __syncthreads();
    if (tid == 0) {
        float t = 0.f;
#pragma unroll
        for (int i = 0; i < 8; i++) t += red[i];
        svar = t * (1.f/2048.f);
    }
    __syncthreads();
    float rstd = rsqrtf(svar + 1e-6f);

    __half hb[8];
#pragma unroll
    for (int i = 0; i < 8; i++) {
        int cc = tid*8 + i;
        float y = (v[i]-mu)*rstd*pw[cc] + pb[cc];
        hb[i] = __float2half_rn(y);
    }
    *(uint4*)&g_xnh[(size_t)row*Dc + tid*8] = *(uint4*)hb;
}

// ---------------------------------------------------------------------------
extern "C" void kernel_launch(void* const* d_in, const int* in_sizes, int n_in,
                              void* d_out, int out_size)
{
    (void)in_sizes; (void)n_in; (void)out_size;
    const float* hs    = (const float*)d_in[0];
    const float* wq_w  = (const float*)d_in[1];
    const float* wq_b  = (const float*)d_in[2];
    const float* wk_w  = (const float*)d_in[3];
    const float* wk_b  = (const float*)d_in[4];
    const float* wv_w  = (const float*)d_in[5];
    const float* wv_b  = (const float*)d_in[6];
    const float* wo_w  = (const float*)d_in[7];
    const float* wo_b  = (const float*)d_in[8];
    const float* tnw   = (const float*)d_in[9];
    const float* tnb   = (const float*)d_in[10];
    const float* lr_w  = (const float*)d_in[11];
    const float* lr_b  = (const float*)d_in[12];
    const float* W1    = (const float*)d_in[13];
    const float* b1    = (const float*)d_in[14];
    const float* pnw   = (const float*)d_in[15];
    const float* pnb   = (const float*)d_in[16];

    float *pq, *pk, *pv;
    __half *ah, *wqh, *wql, *wkh, *wkl, *wvh, *wvl, *woh, *wol, *xnh;
    cudaGetSymbolAddress((void**)&pq,  g_q);
    cudaGetSymbolAddress((void**)&pk,  g_k);
    cudaGetSymbolAddress((void**)&pv,  g_v);
    cudaGetSymbolAddress((void**)&ah,  g_ah);
    cudaGetSymbolAddress((void**)&wqh, g_wqh);
    cudaGetSymbolAddress((void**)&wql, g_wql);
    cudaGetSymbolAddress((void**)&wkh, g_wkh);
    cudaGetSymbolAddress((void**)&wkl, g_wkl);
    cudaGetSymbolAddress((void**)&wvh, g_wvh);
    cudaGetSymbolAddress((void**)&wvl, g_wvl);
    cudaGetSymbolAddress((void**)&woh, g_woh);
    cudaGetSymbolAddress((void**)&wol, g_wol);
    cudaGetSymbolAddress((void**)&xnh, g_xnh);

    cudaFuncSetAttribute(hgemm_kernel,
                         cudaFuncAttributeMaxDynamicSharedMemorySize, HG_SMEM);

    const int nA = Mrows*Dc;     // 16.7M
    const int nW = Dc*Dc;        // 4.2M
    conv_hi_kernel<<<nA/1024, 256>>>(hs, ah, nA);
    conv_hilo_kernel<<<nW/1024, 256>>>(wq_w, wqh, wql, nW);
    conv_hilo_kernel<<<nW/1024, 256>>>(wk_w, wkh, wkl, nW);
    conv_hilo_kernel<<<nW/1024, 256>>>(wv_w, wvh, wvl, nW);
    conv_hilo_kernel<<<nW/1024, 256>>>(wo_w, woh, wol, nW);

    dim3 gg(Dc/128, Mrows/128);   // (16, 64)
    hgemm_kernel<<<gg, 256, HG_SMEM>>>(ah, wqh, wql, wq_b, pq, 1);
    hgemm_kernel<<<gg, 256, HG_SMEM>>>(ah, wkh, wkl, wk_b, pk, 1);
    hgemm_kernel<<<gg, 256, HG_SMEM>>>(ah, wvh, wvl, wv_b, pv, 1);
    lr_gemm_kernel<<<Mrows/64, 256>>>(hs, lr_w, lr_b);
    norm_kernel<<<(Bb*Hh*NMBc*Kc)/8, 256>>>(tnw, tnb);
    scan_kernel<<<Bb*Hh, 256>>>(W1, b1, tnw, tnb);
    postnorm_kernel<<<Mrows, 256>>>(pnw, pnb);
    hgemm_kernel<<<gg, 256, HG_SMEM>>>(xnh, woh, wol, wo_b, (float*)d_out, 0);
}